// round 1
// baseline (speedup 1.0000x reference)
#include <cuda_runtime.h>
#include <math.h>

#define LL 1024
#define BB 128
#define DD 256
#define HH 256

// =====================================================================
// Kernel 1: xproj[m, j] = sum_d X[m,d] * Wx[j,d] + bx[j],  M = L*B
// Tiled fp32 GEMM: BM=128, BN=64, BK=16, 256 threads, 8x4 microtile.
// Writes into d_out (staging area; scan overwrites in place).
// =====================================================================
__global__ __launch_bounds__(256) void xproj_kernel(
    const float* __restrict__ X,
    const float* __restrict__ Wx,
    const float* __restrict__ bx,
    float* __restrict__ C)
{
    __shared__ float As[16][132];   // [k][m], padded
    __shared__ float Bs[16][68];    // [k][n], padded

    const int m0 = blockIdx.x * 128;
    const int n0 = blockIdx.y * 64;
    const int tid = threadIdx.x;
    const int tm = (tid >> 4) * 8;   // 0..120
    const int tn = (tid & 15) * 4;   // 0..60

    float acc[8][4];
#pragma unroll
    for (int i = 0; i < 8; i++)
#pragma unroll
        for (int j = 0; j < 4; j++) acc[i][j] = 0.0f;

    for (int k0 = 0; k0 < DD; k0 += 16) {
        // load A tile: 128 rows x 16 k  (512 float4, 2 per thread)
#pragma unroll
        for (int i = 0; i < 2; i++) {
            int idx  = i * 256 + tid;
            int row  = idx >> 2;
            int col4 = idx & 3;
            float4 v = *(const float4*)(X + (size_t)(m0 + row) * DD + k0 + col4 * 4);
            As[col4 * 4 + 0][row] = v.x;
            As[col4 * 4 + 1][row] = v.y;
            As[col4 * 4 + 2][row] = v.z;
            As[col4 * 4 + 3][row] = v.w;
        }
        // load B tile: 64 rows x 16 k (256 float4, 1 per thread)
        {
            int row  = tid >> 2;
            int col4 = tid & 3;
            float4 v = *(const float4*)(Wx + (size_t)(n0 + row) * DD + k0 + col4 * 4);
            Bs[col4 * 4 + 0][row] = v.x;
            Bs[col4 * 4 + 1][row] = v.y;
            Bs[col4 * 4 + 2][row] = v.z;
            Bs[col4 * 4 + 3][row] = v.w;
        }
        __syncthreads();

#pragma unroll
        for (int k = 0; k < 16; k++) {
            float a[8], bbv[4];
            *(float4*)&a[0] = *(const float4*)&As[k][tm];
            *(float4*)&a[4] = *(const float4*)&As[k][tm + 4];
            *(float4*)&bbv[0] = *(const float4*)&Bs[k][tn];
#pragma unroll
            for (int i = 0; i < 8; i++)
#pragma unroll
                for (int j = 0; j < 4; j++)
                    acc[i][j] = fmaf(a[i], bbv[j], acc[i][j]);
        }
        __syncthreads();
    }

    float4 bxv = *(const float4*)(bx + n0 + tn);
#pragma unroll
    for (int i = 0; i < 8; i++) {
        float4 v;
        v.x = acc[i][0] + bxv.x;
        v.y = acc[i][1] + bxv.y;
        v.z = acc[i][2] + bxv.z;
        v.w = acc[i][3] + bxv.w;
        *(float4*)(C + (size_t)(m0 + tm + i) * HH + n0 + tn) = v;
    }
}

// =====================================================================
// Kernel 2: persistent scan. One CTA per batch element (128 CTAs).
// 512 threads: thread (j = tid&255, half = tid>>8) computes the
// partial dot over k in [half*128, half*128+128) for neuron j.
// Weights: k in [kb, kb+80) in registers (80 floats/thread = 160KB/CTA),
//          k in [kb+80, kb+128) in shared (96KB, [k][j] conflict-free).
// h ping-pongs in shared; xp read from d_out and overwritten with h_t.
// =====================================================================
__global__ __launch_bounds__(512, 1) void scan_kernel(
    const float* __restrict__ h0,
    const float* __restrict__ Wh,
    const float* __restrict__ bh,
    float* __restrict__ out,
    int hasFinal)
{
    extern __shared__ float smem[];
    float4* Ws4  = (float4*)smem;            // 24*256 float4 = 96 KB
    float*  hbuf = smem + 24 * 256 * 4;      // 2*256 floats (ping-pong)
    float*  part = hbuf + 512;               // 256 floats
    float*  bh_s = part + 256;               // 256 floats

    const int tid  = threadIdx.x;
    const int j    = tid & 255;
    const int half = tid >> 8;
    const int b    = blockIdx.x;
    const int kb   = half * 128;

    // register-resident weights: k in [kb, kb+80)
    float4 wr[20];
    const float4* wrow = (const float4*)(Wh + (size_t)j * HH + kb);
#pragma unroll
    for (int i = 0; i < 20; i++) wr[i] = wrow[i];

    // shared weights: g<12 -> k = 80+4g (half 0), g>=12 -> k = 208+4(g-12) (half 1)
    for (int idx = tid; idx < 24 * 256; idx += 512) {
        int g  = idx >> 8;
        int jj = idx & 255;
        int kk = (g < 12) ? (80 + 4 * g) : (208 + 4 * (g - 12));
        Ws4[g * 256 + jj] = *(const float4*)(Wh + (size_t)jj * HH + kk);
    }
    if (tid < 256) {
        hbuf[tid] = h0[(size_t)b * HH + tid];
        bh_s[tid] = bh[tid];
    }
    __syncthreads();

    int cur = 0;
    for (int t = 0; t < LL; ++t) {
        float xp = 0.0f;
        if (!half) xp = out[(size_t)t * (BB * HH) + (size_t)b * HH + j];

        const float4* h4 = (const float4*)(hbuf + cur * 256 + kb);
        float a0 = 0.f, a1 = 0.f, a2 = 0.f, a3 = 0.f;
#pragma unroll
        for (int i = 0; i < 20; i++) {
            float4 hv = h4[i];
            a0 = fmaf(wr[i].x, hv.x, a0);
            a1 = fmaf(wr[i].y, hv.y, a1);
            a2 = fmaf(wr[i].z, hv.z, a2);
            a3 = fmaf(wr[i].w, hv.w, a3);
        }
        const float4* wsp = Ws4 + half * 12 * 256 + j;
#pragma unroll
        for (int g = 0; g < 12; g++) {
            float4 wv = wsp[g * 256];
            float4 hv = h4[20 + g];
            a0 = fmaf(wv.x, hv.x, a0);
            a1 = fmaf(wv.y, hv.y, a1);
            a2 = fmaf(wv.z, hv.z, a2);
            a3 = fmaf(wv.w, hv.w, a3);
        }
        float acc = (a0 + a1) + (a2 + a3);

        if (half) part[j] = acc;
        __syncthreads();

        if (!half) {
            float v  = acc + part[j] + xp + bh_s[j];
            float hn = tanhf(v);
            hbuf[(cur ^ 1) * 256 + j] = hn;
            out[(size_t)t * (BB * HH) + (size_t)b * HH + j] = hn;
            if (hasFinal && t == LL - 1)
                out[(size_t)LL * BB * HH + (size_t)b * HH + j] = hn;
        }
        __syncthreads();
        cur ^= 1;
    }
}

// =====================================================================
// launch
// =====================================================================
extern "C" void kernel_launch(void* const* d_in, const int* in_sizes, int n_in,
                              void* d_out, int out_size)
{
    const float* x   = (const float*)d_in[0];  // [L,B,D]
    const float* h0  = (const float*)d_in[1];  // [B,H]
    const float* Wxw = (const float*)d_in[2];  // [H,D]
    const float* Wxb = (const float*)d_in[3];  // [H]
    const float* Whw = (const float*)d_in[4];  // [H,H]
    const float* Whb = (const float*)d_in[5];  // [H]
    float* out = (float*)d_out;

    (void)in_sizes; (void)n_in;

    const int smemScan = (24 * 256 * 4 + 512 + 256 + 256) * (int)sizeof(float); // 102400
    cudaFuncSetAttribute(scan_kernel, cudaFuncAttributeMaxDynamicSharedMemorySize, smemScan);

    // xproj -> stage into d_out
    dim3 g1(LL * BB / 128, HH / 64);   // (1024, 4)
    xproj_kernel<<<g1, 256>>>(x, Wxw, Wxb, out);

    const int hasFinal = (out_size >= LL * BB * HH + BB * HH) ? 1 : 0;
    scan_kernel<<<BB, 512, smemScan>>>(h0, Whw, Whb, out, hasFinal);
}